// round 15
// baseline (speedup 1.0000x reference)
#include <cuda_runtime.h>
#include <cuda_bf16.h>
#include <math.h>
#include <stdint.h>

// ---------------- static scratch (no allocation allowed) ----------------
__device__ float g_enc1[8*256*256*16];
__device__ float g_enc2[8*128*128*16];
__device__ float g_enc3[8*64*64*32];
__device__ float g_dec0[8*256*256*64];               // decoder fp32 ping
__device__ float g_dec1[8*256*256*64];               // decoder fp32 pong
__device__ __align__(16) __nv_bfloat16 g_xh0[16777216];  // bf16-hi ping (max 262144 px * 64)
__device__ __align__(16) __nv_bfloat16 g_xl0[16777216];  // bf16-lo ping
__device__ __align__(16) __nv_bfloat16 g_xh1[16777216];  // bf16-hi pong
__device__ __align__(16) __nv_bfloat16 g_xl1[16777216];  // bf16-lo pong
__device__ __align__(16) __nv_bfloat16 g_wpre[9*2*4096]; // deconv weights bf16 [tap][hi|lo][co][ci]
__device__ float g_m0[8*256*256];
__device__ float g_m1[8*256*256];
__device__ float g_loss;

__device__ __forceinline__ float gelu_f(float x) {
    float x3 = x * x * x;
    return 0.5f * x * (1.0f + tanhf(0.7978845608028654f * (x + 0.044715f * x3)));
}
__device__ __forceinline__ uint32_t smem_u32(const void* p) {
    uint32_t a;
    asm("{ .reg .u64 t; cvta.to.shared.u64 t, %1; cvt.u32.u64 %0, t; }" : "=r"(a) : "l"(p));
    return a;
}
__device__ __forceinline__ void ldsm4(uint32_t* r, uint32_t addr) {
    asm volatile("ldmatrix.sync.aligned.m8n8.x4.shared.b16 {%0,%1,%2,%3}, [%4];"
                 : "=r"(r[0]), "=r"(r[1]), "=r"(r[2]), "=r"(r[3]) : "r"(addr));
}
__device__ __forceinline__ void mma16816(float* c, const uint32_t* a, uint32_t b0, uint32_t b1) {
    asm volatile("mma.sync.aligned.m16n8k16.row.col.f32.bf16.bf16.f32 "
                 "{%0,%1,%2,%3}, {%4,%5,%6,%7}, {%8,%9}, {%0,%1,%2,%3};"
                 : "+f"(c[0]), "+f"(c[1]), "+f"(c[2]), "+f"(c[3])
                 : "r"(a[0]), "r"(a[1]), "r"(a[2]), "r"(a[3]), "r"(b0), "r"(b1));
}

// ---------------- encoder layer 1: 1->16, stride 1, LN, gelu ----------------
__global__ void conv1_trio(const float* __restrict__ img, const float* __restrict__ w,
                           const float* __restrict__ bias, float* __restrict__ out) {
    __shared__ float ws[144];
    __shared__ float bs[16];
    int tid = threadIdx.x;
    if (tid < 144) ws[tid] = w[tid];
    if (tid < 16)  bs[tid] = bias[tid];
    __syncthreads();
    int p = blockIdx.x * 256 + tid;
    int b = p >> 16; int rem = p & 65535;
    int y = rem >> 8; int x = rem & 255;
    float v[16];
#pragma unroll
    for (int i = 0; i < 16; i++) v[i] = bs[i];
    const float* ib = img + (long)b * 65536;
#pragma unroll
    for (int ky = 0; ky < 3; ky++) {
        int iy = y + ky - 1; if ((unsigned)iy >= 256u) continue;
#pragma unroll
        for (int kx = 0; kx < 3; kx++) {
            int ix = x + kx - 1; if ((unsigned)ix >= 256u) continue;
            float xv = ib[iy * 256 + ix];
            const float* wr = &ws[(ky * 3 + kx) * 16];
#pragma unroll
            for (int c = 0; c < 16; c++) v[c] = fmaf(xv, wr[c], v[c]);
        }
    }
    float mu = 0.f;
#pragma unroll
    for (int c = 0; c < 16; c++) mu += v[c];
    mu *= (1.0f / 16.0f);
    float var = 0.f;
#pragma unroll
    for (int c = 0; c < 16; c++) { float d = v[c] - mu; var = fmaf(d, d, var); }
    var *= (1.0f / 16.0f);
    float r = rsqrtf(var + 1e-6f);
    float* o = out + (long)p * 16;
#pragma unroll
    for (int c = 0; c < 16; c++) o[c] = gelu_f((v[c] - mu) * r);
}

// ------------- generic stride-2 conv trio (SAME pad: lo=0, hi=1) -------------
// If XH/XL non-null, also writes bf16 hi/lo of the gelu'd output (deconv feed).
template<int CI, int CO, int HIN, int CHUNK>
__global__ void conv_s2_trio(const float* __restrict__ X, const float* __restrict__ W,
                             const float* __restrict__ bias, float* __restrict__ Y,
                             __nv_bfloat16* __restrict__ XH, __nv_bfloat16* __restrict__ XL) {
    constexpr int HOUT = HIN / 2;
    constexpr int CO4 = CO / 4;
    __shared__ float4 ws[9 * CHUNK * CO4];
    int tid = threadIdx.x;
    int p = blockIdx.x * 256 + tid;
    int b = p / (HOUT * HOUT); int rem = p % (HOUT * HOUT);
    int y = rem / HOUT, x = rem % HOUT;
    float4 acc[CO4];
#pragma unroll
    for (int i = 0; i < CO4; i++) acc[i] = make_float4(0.f, 0.f, 0.f, 0.f);
    const float4* W4 = (const float4*)W;
    for (int c0 = 0; c0 < CI; c0 += CHUNK) {
        __syncthreads();
        for (int t = tid; t < 9 * CHUNK * CO4; t += 256) {
            int co4 = t % CO4; int ci = (t / CO4) % CHUNK; int tap = t / (CO4 * CHUNK);
            ws[t] = W4[((long)tap * CI + c0 + ci) * CO4 + co4];
        }
        __syncthreads();
        for (int ky = 0; ky < 3; ky++) {
            int iy = 2 * y + ky; if (iy >= HIN) continue;
            for (int kx = 0; kx < 3; kx++) {
                int ix = 2 * x + kx; if (ix >= HIN) continue;
                const float4* xp = (const float4*)(X + ((((long)b * HIN + iy) * HIN + ix) * CI + c0));
                const float4* wt = &ws[(ky * 3 + kx) * CHUNK * CO4];
#pragma unroll
                for (int q = 0; q < CHUNK / 4; q++) {
                    float4 xv = xp[q];
#pragma unroll
                    for (int l = 0; l < 4; l++) {
                        float xs = (l == 0) ? xv.x : (l == 1) ? xv.y : (l == 2) ? xv.z : xv.w;
                        const float4* wr = wt + (q * 4 + l) * CO4;
#pragma unroll
                        for (int co = 0; co < CO4; co++) {
                            acc[co].x = fmaf(xs, wr[co].x, acc[co].x);
                            acc[co].y = fmaf(xs, wr[co].y, acc[co].y);
                            acc[co].z = fmaf(xs, wr[co].z, acc[co].z);
                            acc[co].w = fmaf(xs, wr[co].w, acc[co].w);
                        }
                    }
                }
            }
        }
    }
    float mu = 0.f;
#pragma unroll
    for (int i = 0; i < CO4; i++) {
        float4 bb = __ldg(((const float4*)bias) + i);
        acc[i].x += bb.x; acc[i].y += bb.y; acc[i].z += bb.z; acc[i].w += bb.w;
        mu += acc[i].x + acc[i].y + acc[i].z + acc[i].w;
    }
    mu *= (1.0f / CO);
    float var = 0.f;
#pragma unroll
    for (int i = 0; i < CO4; i++) {
        float dx = acc[i].x - mu, dy = acc[i].y - mu, dz = acc[i].z - mu, dw = acc[i].w - mu;
        var += dx * dx + dy * dy + dz * dz + dw * dw;
    }
    var *= (1.0f / CO);
    float r = rsqrtf(var + 1e-6f);
    float4* o = (float4*)(Y + (long)p * CO);
#pragma unroll
    for (int i = 0; i < CO4; i++) {
        float4 g = make_float4(gelu_f((acc[i].x - mu) * r), gelu_f((acc[i].y - mu) * r),
                               gelu_f((acc[i].z - mu) * r), gelu_f((acc[i].w - mu) * r));
        o[i] = g;
        if (XH) {
            __nv_bfloat162 ha = __floats2bfloat162_rn(g.x, g.y);
            __nv_bfloat162 hb = __floats2bfloat162_rn(g.z, g.w);
            __nv_bfloat162 la = __floats2bfloat162_rn(g.x - __bfloat162float(ha.x),
                                                      g.y - __bfloat162float(ha.y));
            __nv_bfloat162 lb = __floats2bfloat162_rn(g.z - __bfloat162float(hb.x),
                                                      g.w - __bfloat162float(hb.y));
            ((__nv_bfloat162*)(XH + (long)p * CO))[i * 2 + 0] = ha;
            ((__nv_bfloat162*)(XH + (long)p * CO))[i * 2 + 1] = hb;
            ((__nv_bfloat162*)(XL + (long)p * CO))[i * 2 + 0] = la;
            ((__nv_bfloat162*)(XL + (long)p * CO))[i * 2 + 1] = lb;
        }
    }
}

// ---- preconvert deconv weights: fp32 HWIO -> bf16 hi/lo [tap][part][co][ci] ----
__global__ void preconv_w(const float* __restrict__ up_w, __nv_bfloat16* __restrict__ dst) {
    int idx = blockIdx.x * 256 + threadIdx.x;
    if (idx >= 9 * 4096) return;
    int tap = idx >> 12; int r = idx & 4095;
    int ci = r >> 6; int co = r & 63;
    float w = up_w[idx];                           // [tap][ci][co]
    __nv_bfloat16 hi = __float2bfloat16(w);
    __nv_bfloat16 lo = __float2bfloat16(w - __bfloat162float(hi));
    dst[(tap * 2 + 0) * 4096 + co * 64 + ci] = hi;
    dst[(tap * 2 + 1) * 4096 + co * 64 + ci] = lo;
}

// ------------- decoder conv_transpose 64->64: mma.sync bf16 3-pass GEMM -------------
// CTA: M=128 px x N=64 co, K=64 per tap. 8 warps = 4(M) x 2(N), warp tile 32x32.
// smem rows 128B, XOR-16B swizzle (chunk ^ (row&7)) -> conflict-free ldmatrix.
template<int DIM, int PAR>
__global__ __launch_bounds__(256, 2)
void deconv_mma(const __nv_bfloat16* __restrict__ XHb, const __nv_bfloat16* __restrict__ XLb,
                float* __restrict__ Y,
                __nv_bfloat16* __restrict__ OH, __nv_bfloat16* __restrict__ OL,
                const __nv_bfloat16* __restrict__ Wg, const float* __restrict__ bias,
                int h_in, int w_in, int hw_sh, int w_sh, int wcvt) {
    constexpr int NTAP = (PAR == 0) ? 6 : 3;
    __shared__ __align__(16) unsigned char sm[49152];   // AH 0 | AL 16K | WH 32K | WL 40K
    uint32_t sb = smem_u32(sm);
    int tid = threadIdx.x;
    int lane = tid & 31, wid = tid >> 5;
    int mw = wid & 3, nw = wid >> 2;

    int q0 = blockIdx.x * 128;
    // X staging role: part (hi/lo), one 128B row each
    int part = tid >> 7, srow = tid & 127;
    int qg = q0 + srow;
    int bg = qg >> hw_sh; int remg = qg & ((1 << hw_sh) - 1);
    int yg = remg >> w_sh; int xg = remg & (w_in - 1);
    const __nv_bfloat16* Xsrc = part ? XLb : XHb;
    uint32_t a_dst = sb + part * 16384 + srow * 128;
    int sxor = srow & 7;
    // W staging role: 4 chunks of one row half
    int wpart = tid >> 7, wrow = (tid >> 1) & 63, wjb = (tid & 1) * 4;
    uint32_t w_dst = sb + 32768 + wpart * 8192 + wrow * 128;
    int wxor = wrow & 7;

    float c[2][4][4];
#pragma unroll
    for (int mt = 0; mt < 2; mt++)
#pragma unroll
        for (int nt = 0; nt < 4; nt++)
#pragma unroll
            for (int i = 0; i < 4; i++) c[mt][nt][i] = 0.f;

#pragma unroll
    for (int t = 0; t < NTAP; t++) {
        // tap geometry (compile-time per t)
        int dy, dx, wtap;
        if (DIM == 0) {
            if (PAR == 0) { if (t < 3) { dy = -1; dx = t - 1; wtap = t; }
                            else       { dy = 0;  dx = t - 4; wtap = 3 + t; } }
            else          { dy = 0; dx = t - 1; wtap = 3 + t; }
        } else {
            if (PAR == 0) { if (t < 3) { dy = t - 1; dx = -1; wtap = 3 * t; }
                            else       { dy = t - 4; dx = 0;  wtap = 3 * t - 7; } }
            else          { dy = t - 1; dx = 0; wtap = 3 * t + 1; }
        }
        __syncthreads();
        // stage W tile (hi+lo 16KB)
        {
            const float4* src = (const float4*)(Wg + ((long)(wtap * 2 + wpart) * 4096 + wrow * 64));
#pragma unroll
            for (int j = 0; j < 4; j++) {
                float4 v = src[wjb + j];
                *(float4*)(sm + (w_dst - sb) + (((wjb + j) ^ wxor) << 4)) = v;
            }
        }
        // stage X tile (hi/lo 32KB), zero-filled at boundaries
        {
            int sy = yg + dy, sx = xg + dx;
            bool valid = (sy >= 0) && (sy < h_in) && (sx >= 0) && (sx < w_in);
            long pxp = ((long)bg << hw_sh) + ((long)sy << w_sh) + sx;
            const float4* src = (const float4*)(Xsrc + (pxp << 6));
#pragma unroll
            for (int j = 0; j < 8; j++) {
                float4 v = valid ? src[j] : make_float4(0.f, 0.f, 0.f, 0.f);
                *(float4*)(sm + (a_dst - sb) + ((j ^ sxor) << 4)) = v;
            }
        }
        __syncthreads();
        // compute: K=64 -> 4 chunks of k16
        int lr = lane & 15, lh = lane >> 4;
        int rx = lr & 7;
#pragma unroll
        for (int kc = 0; kc < 4; kc++) {
            uint32_t ch = (uint32_t)(((kc * 2 + lh) ^ rx) << 4);
            uint32_t ah[2][4], al[2][4], wh[2][4], wl[2][4];
            ldsm4(ah[0], sb + (mw * 32 + lr) * 128 + ch);
            ldsm4(ah[1], sb + (mw * 32 + 16 + lr) * 128 + ch);
            ldsm4(al[0], sb + 16384 + (mw * 32 + lr) * 128 + ch);
            ldsm4(al[1], sb + 16384 + (mw * 32 + 16 + lr) * 128 + ch);
            ldsm4(wh[0], sb + 32768 + (nw * 32 + lr) * 128 + ch);
            ldsm4(wh[1], sb + 32768 + (nw * 32 + 16 + lr) * 128 + ch);
            ldsm4(wl[0], sb + 40960 + (nw * 32 + lr) * 128 + ch);
            ldsm4(wl[1], sb + 40960 + (nw * 32 + 16 + lr) * 128 + ch);
#pragma unroll
            for (int mt = 0; mt < 2; mt++)
#pragma unroll
                for (int nt = 0; nt < 4; nt++) {
                    int bt = nt >> 1, io = nt & 1;
                    mma16816(c[mt][nt], ah[mt], wh[bt][io], wh[bt][io + 2]);  // xh*wh
                    mma16816(c[mt][nt], ah[mt], wl[bt][io], wl[bt][io + 2]);  // xh*wl
                    mma16816(c[mt][nt], al[mt], wh[bt][io], wh[bt][io + 2]);  // xl*wh
                }
        }
    }

    // epilogue: bias + gelu, write fp32 Y + optional bf16 hi/lo feed
    int h_out = (DIM == 0) ? (h_in << 1) : h_in;
    int w_out = (DIM == 0) ? w_in : (w_in << 1);
#pragma unroll
    for (int mt = 0; mt < 2; mt++)
#pragma unroll
        for (int hr = 0; hr < 2; hr++) {
            int row = mw * 32 + mt * 16 + (lane >> 2) + hr * 8;
            int q = q0 + row;
            int b = q >> hw_sh; int rem = q & ((1 << hw_sh) - 1);
            int y = rem >> w_sh; int x = rem & (w_in - 1);
            int oy = (DIM == 0) ? (2 * y + PAR) : y;
            int ox = (DIM == 0) ? x : (2 * x + PAR);
            long pxo = (((long)b * h_out + oy) * w_out + ox);
            float* yp = Y + (pxo << 6);
#pragma unroll
            for (int nt = 0; nt < 4; nt++) {
                int n = nw * 32 + nt * 8 + (lane & 3) * 2;
                float2 bb = __ldg((const float2*)(bias + n));
                float g0 = gelu_f(c[mt][nt][hr * 2 + 0] + bb.x);
                float g1 = gelu_f(c[mt][nt][hr * 2 + 1] + bb.y);
                *(float2*)(yp + n) = make_float2(g0, g1);
                if (wcvt) {
                    __nv_bfloat162 h2 = __floats2bfloat162_rn(g0, g1);
                    __nv_bfloat162 l2 = __floats2bfloat162_rn(g0 - __bfloat162float(h2.x),
                                                              g1 - __bfloat162float(h2.y));
                    *(__nv_bfloat162*)(OH + (pxo << 6) + n) = h2;
                    *(__nv_bfloat162*)(OL + (pxo << 6) + n) = l2;
                }
            }
        }
}

// ------- mask conv(64->4) + softmax + entropy + img pool + masks update + loss -------
__global__ void mask_loss(const float* __restrict__ D, const float* __restrict__ mw,
                          const float* __restrict__ mb, const float* __restrict__ img,
                          const float* __restrict__ masks_in, float* __restrict__ masks_out,
                          int h, int w, int dim, float scale, float* __restrict__ loss) {
    __shared__ float4 ws[576];
    __shared__ float red[256];
    int tid = threadIdx.x;
    const float4* mw4 = (const float4*)mw;
    for (int t = tid; t < 576; t += 256) ws[t] = mw4[t];
    __syncthreads();
    int p = blockIdx.x * 256 + tid;
    int hw = h * w;
    int b = p / hw; int rem = p % hw; int oy = rem / w; int ox = rem % w;
    float4 lg = make_float4(__ldg(mb + 0), __ldg(mb + 1), __ldg(mb + 2), __ldg(mb + 3));
    for (int ky = 0; ky < 3; ky++) {
        int iy = oy + ky - 1; if ((unsigned)iy >= (unsigned)h) continue;
        for (int kx = 0; kx < 3; kx++) {
            int ix = ox + kx - 1; if ((unsigned)ix >= (unsigned)w) continue;
            const float4* xp = (const float4*)(D + ((((long)b * h + iy) * w + ix) << 6));
            const float4* wt = &ws[(ky * 3 + kx) * 64];
#pragma unroll
            for (int q = 0; q < 16; q++) {
                float4 xv = xp[q];
                const float4* wr = wt + q * 4;
                lg.x = fmaf(xv.x, wr[0].x, lg.x); lg.y = fmaf(xv.x, wr[0].y, lg.y);
                lg.z = fmaf(xv.x, wr[0].z, lg.z); lg.w = fmaf(xv.x, wr[0].w, lg.w);
                lg.x = fmaf(xv.y, wr[1].x, lg.x); lg.y = fmaf(xv.y, wr[1].y, lg.y);
                lg.z = fmaf(xv.y, wr[1].z, lg.z); lg.w = fmaf(xv.y, wr[1].w, lg.w);
                lg.x = fmaf(xv.z, wr[2].x, lg.x); lg.y = fmaf(xv.z, wr[2].y, lg.y);
                lg.z = fmaf(xv.z, wr[2].z, lg.z); lg.w = fmaf(xv.z, wr[2].w, lg.w);
                lg.x = fmaf(xv.w, wr[3].x, lg.x); lg.y = fmaf(xv.w, wr[3].y, lg.y);
                lg.z = fmaf(xv.w, wr[3].z, lg.z); lg.w = fmaf(xv.w, wr[3].w, lg.w);
            }
        }
    }
    float m = fmaxf(fmaxf(lg.x, lg.y), fmaxf(lg.z, lg.w));
    float e0 = expf(lg.x - m), e1 = expf(lg.y - m), e2 = expf(lg.z - m), e3 = expf(lg.w - m);
    float inv = 1.0f / (e0 + e1 + e2 + e3);
    float p0 = e0 * inv, p1 = e1 * inv, p2 = e2 * inv, p3 = e3 * inv;
    float sel = p1 + 2.0f * p2 + 3.0f * p3;
    float ent = -(p0 * logf(p0 + 1e-8f) + p1 * logf(p1 + 1e-8f)
                + p2 * logf(p2 + 1e-8f) + p3 * logf(p3 + 1e-8f));
    int ph = 256 / h, pw = 256 / w;
    const float* ip = img + (((long)b * 256 + (long)oy * ph) * 256 + (long)ox * pw);
    float s = 0.f;
    for (int a = 0; a < ph; a++)
        for (int cc = 0; cc < pw; cc++) s += ip[a * 256 + cc];
    float ids = s / (float)(ph * pw);
    float d = sel * (1.0f / 3.0f) - ids;
    long src;
    if (dim == 0) src = ((long)b * (h >> 1) + (oy >> 1)) * w + ox;
    else          src = ((long)b * h + oy) * (w >> 1) + (ox >> 1);
    masks_out[p] = masks_in[src] + 0.25f * sel;
    red[tid] = ent + d * d;
    __syncthreads();
    for (int off = 128; off > 0; off >>= 1) {
        if (tid < off) red[tid] += red[tid + off];
        __syncthreads();
    }
    if (tid == 0) atomicAdd(loss, red[0] * scale);
}

__global__ void zero_loss_k() { g_loss = 0.0f; }
__global__ void finalize_k(float* out) { out[0] = g_loss; }

static inline int ilog2i(int v) { int s = 0; while ((1 << s) < v) s++; return s; }

// ---------------------------------------------------------------------------
extern "C" void kernel_launch(void* const* d_in, const int* in_sizes, int n_in,
                              void* d_out, int out_size) {
    const float* image  = (const float*)d_in[0];
    const float* w1 = (const float*)d_in[2];  const float* b1 = (const float*)d_in[3];
    const float* w2 = (const float*)d_in[4];  const float* b2 = (const float*)d_in[5];
    const float* w3 = (const float*)d_in[6];  const float* b3 = (const float*)d_in[7];
    const float* w4 = (const float*)d_in[8];  const float* b4 = (const float*)d_in[9];
    const float* up_w = (const float*)d_in[10]; const float* up_b = (const float*)d_in[11];
    const float* mask_w = (const float*)d_in[12]; const float* mask_b = (const float*)d_in[13];
    const float* masks0 = (const float*)d_in[14];
    float* out = (float*)d_out;

    float *e1, *e2, *e3, *dc0, *dc1, *m0, *m1, *lossp;
    __nv_bfloat16 *xh0, *xl0, *xh1, *xl1, *wpre;
    cudaGetSymbolAddress((void**)&e1,  g_enc1);
    cudaGetSymbolAddress((void**)&e2,  g_enc2);
    cudaGetSymbolAddress((void**)&e3,  g_enc3);
    cudaGetSymbolAddress((void**)&dc0, g_dec0);
    cudaGetSymbolAddress((void**)&dc1, g_dec1);
    cudaGetSymbolAddress((void**)&m0,  g_m0);
    cudaGetSymbolAddress((void**)&m1,  g_m1);
    cudaGetSymbolAddress((void**)&lossp, g_loss);
    cudaGetSymbolAddress((void**)&xh0, g_xh0);
    cudaGetSymbolAddress((void**)&xl0, g_xl0);
    cudaGetSymbolAddress((void**)&xh1, g_xh1);
    cudaGetSymbolAddress((void**)&xl1, g_xl1);
    cudaGetSymbolAddress((void**)&wpre, g_wpre);

    zero_loss_k<<<1, 1>>>();
    preconv_w<<<(9 * 4096 + 255) / 256, 256>>>(up_w, wpre);

    conv1_trio<<<(8 * 256 * 256) / 256, 256>>>(image, w1, b1, e1);
    conv_s2_trio<16, 16, 256, 16><<<(8 * 128 * 128) / 256, 256>>>(e1, w2, b2, e2, nullptr, nullptr);
    conv_s2_trio<16, 32, 128, 16><<<(8 * 64 * 64) / 256, 256>>>(e2, w3, b3, e3, nullptr, nullptr);
    conv_s2_trio<32, 64, 64, 16><<<(8 * 32 * 32) / 256, 256>>>(e3, w4, b4, dc0, xh0, xl0);

    const float lws[6] = {0.1f, 0.1f, 0.5f, 0.5f, 1.0f, 1.0f};
    float* ydst = dc1;
    const float* min_ = masks0;
    float* mbuf[2] = {m0, m1};
    __nv_bfloat16* xh[2] = {xh0, xh1};
    __nv_bfloat16* xl[2] = {xl0, xl1};
    int h = 32, w = 32;
    for (int i = 0; i < 6; i++) {
        int dim = i % 2;
        int ho = (dim == 0) ? 2 * h : h;
        int wo = (dim == 0) ? w : 2 * w;
        int px = 8 * ho * wo;
        int cls_px = 8 * h * w;
        int blocks = cls_px / 128;
        int hw_sh = ilog2i(h * w), w_sh = ilog2i(w);
        __nv_bfloat16* ih = xh[i & 1];  __nv_bfloat16* il = xl[i & 1];
        __nv_bfloat16* oh = xh[(i + 1) & 1]; __nv_bfloat16* ol = xl[(i + 1) & 1];
        int wcvt = (i < 5) ? 1 : 0;
        if (dim == 0) {
            deconv_mma<0, 0><<<blocks, 256>>>(ih, il, ydst, oh, ol, wpre, up_b, h, w, hw_sh, w_sh, wcvt);
            deconv_mma<0, 1><<<blocks, 256>>>(ih, il, ydst, oh, ol, wpre, up_b, h, w, hw_sh, w_sh, wcvt);
        } else {
            deconv_mma<1, 0><<<blocks, 256>>>(ih, il, ydst, oh, ol, wpre, up_b, h, w, hw_sh, w_sh, wcvt);
            deconv_mma<1, 1><<<blocks, 256>>>(ih, il, ydst, oh, ol, wpre, up_b, h, w, hw_sh, w_sh, wcvt);
        }
        float* mout = (i == 5) ? (out + 1) : mbuf[i % 2];
        float scale = lws[i] / (float)px;
        mask_loss<<<px / 256, 256>>>(ydst, mask_w, mask_b, image, min_, mout,
                                     ho, wo, dim, scale, lossp);
        min_ = mout;
        ydst = (ydst == dc1) ? dc0 : dc1;
        h = ho; w = wo;
    }
    finalize_k<<<1, 1>>>(out);
}

// round 17
// speedup vs baseline: 1.2652x; 1.2652x over previous
#include <cuda_runtime.h>
#include <math.h>
#include <stdint.h>

// ---------------- static scratch (no allocation allowed) ----------------
__device__ float g_enc1[8*256*256*16];   // after trio1
__device__ float g_enc2[8*128*128*16];   // after trio2
__device__ float g_enc3[8*64*64*32];     // after trio3
__device__ float g_dec0[8*256*256*64];   // decoder ping
__device__ float g_dec1[8*256*256*64];   // decoder pong
__device__ float g_m0[8*256*256];        // masks ping
__device__ float g_m1[8*256*256];        // masks pong
__device__ float g_loss;

__device__ __forceinline__ float gelu_f(float x) {
    float x3 = x * x * x;
    return 0.5f * x * (1.0f + tanhf(0.7978845608028654f * (x + 0.044715f * x3)));
}

// ---------------- encoder layer 1: 1->16, stride 1, LN, gelu ----------------
__global__ void conv1_trio(const float* __restrict__ img, const float* __restrict__ w,
                           const float* __restrict__ bias, float* __restrict__ out) {
    __shared__ float ws[144];
    __shared__ float bs[16];
    int tid = threadIdx.x;
    if (tid < 144) ws[tid] = w[tid];
    if (tid < 16)  bs[tid] = bias[tid];
    __syncthreads();
    int p = blockIdx.x * 256 + tid;
    int b = p >> 16; int rem = p & 65535;
    int y = rem >> 8; int x = rem & 255;
    float v[16];
#pragma unroll
    for (int i = 0; i < 16; i++) v[i] = bs[i];
    const float* ib = img + (long)b * 65536;
#pragma unroll
    for (int ky = 0; ky < 3; ky++) {
        int iy = y + ky - 1; if ((unsigned)iy >= 256u) continue;
#pragma unroll
        for (int kx = 0; kx < 3; kx++) {
            int ix = x + kx - 1; if ((unsigned)ix >= 256u) continue;
            float xv = ib[iy * 256 + ix];
            const float* wr = &ws[(ky * 3 + kx) * 16];
#pragma unroll
            for (int c = 0; c < 16; c++) v[c] = fmaf(xv, wr[c], v[c]);
        }
    }
    float mu = 0.f;
#pragma unroll
    for (int c = 0; c < 16; c++) mu += v[c];
    mu *= (1.0f / 16.0f);
    float var = 0.f;
#pragma unroll
    for (int c = 0; c < 16; c++) { float d = v[c] - mu; var = fmaf(d, d, var); }
    var *= (1.0f / 16.0f);
    float r = rsqrtf(var + 1e-6f);
    float* o = out + (long)p * 16;
#pragma unroll
    for (int c = 0; c < 16; c++) o[c] = gelu_f((v[c] - mu) * r);
}

// ------------- generic stride-2 conv trio (SAME pad: lo=0, hi=1) -------------
template<int CI, int CO, int HIN, int CHUNK>
__global__ void conv_s2_trio(const float* __restrict__ X, const float* __restrict__ W,
                             const float* __restrict__ bias, float* __restrict__ Y) {
    constexpr int HOUT = HIN / 2;
    constexpr int CO4 = CO / 4;
    __shared__ float4 ws[9 * CHUNK * CO4];
    int tid = threadIdx.x;
    int p = blockIdx.x * 256 + tid;
    int b = p / (HOUT * HOUT); int rem = p % (HOUT * HOUT);
    int y = rem / HOUT, x = rem % HOUT;
    float4 acc[CO4];
#pragma unroll
    for (int i = 0; i < CO4; i++) acc[i] = make_float4(0.f, 0.f, 0.f, 0.f);
    const float4* W4 = (const float4*)W;
    for (int c0 = 0; c0 < CI; c0 += CHUNK) {
        __syncthreads();
        for (int t = tid; t < 9 * CHUNK * CO4; t += 256) {
            int co4 = t % CO4; int ci = (t / CO4) % CHUNK; int tap = t / (CO4 * CHUNK);
            ws[t] = W4[((long)tap * CI + c0 + ci) * CO4 + co4];
        }
        __syncthreads();
        for (int ky = 0; ky < 3; ky++) {
            int iy = 2 * y + ky; if (iy >= HIN) continue;
            for (int kx = 0; kx < 3; kx++) {
                int ix = 2 * x + kx; if (ix >= HIN) continue;
                const float4* xp = (const float4*)(X + ((((long)b * HIN + iy) * HIN + ix) * CI + c0));
                const float4* wt = &ws[(ky * 3 + kx) * CHUNK * CO4];
#pragma unroll
                for (int q = 0; q < CHUNK / 4; q++) {
                    float4 xv = xp[q];
#pragma unroll
                    for (int l = 0; l < 4; l++) {
                        float xs = (l == 0) ? xv.x : (l == 1) ? xv.y : (l == 2) ? xv.z : xv.w;
                        const float4* wr = wt + (q * 4 + l) * CO4;
#pragma unroll
                        for (int co = 0; co < CO4; co++) {
                            acc[co].x = fmaf(xs, wr[co].x, acc[co].x);
                            acc[co].y = fmaf(xs, wr[co].y, acc[co].y);
                            acc[co].z = fmaf(xs, wr[co].z, acc[co].z);
                            acc[co].w = fmaf(xs, wr[co].w, acc[co].w);
                        }
                    }
                }
            }
        }
    }
    float mu = 0.f;
#pragma unroll
    for (int i = 0; i < CO4; i++) {
        float4 bb = __ldg(((const float4*)bias) + i);
        acc[i].x += bb.x; acc[i].y += bb.y; acc[i].z += bb.z; acc[i].w += bb.w;
        mu += acc[i].x + acc[i].y + acc[i].z + acc[i].w;
    }
    mu *= (1.0f / CO);
    float var = 0.f;
#pragma unroll
    for (int i = 0; i < CO4; i++) {
        float dx = acc[i].x - mu, dy = acc[i].y - mu, dz = acc[i].z - mu, dw = acc[i].w - mu;
        var += dx * dx + dy * dy + dz * dz + dw * dw;
    }
    var *= (1.0f / CO);
    float r = rsqrtf(var + 1e-6f);
    float4* o = (float4*)(Y + (long)p * CO);
#pragma unroll
    for (int i = 0; i < CO4; i++) {
        o[i] = make_float4(gelu_f((acc[i].x - mu) * r), gelu_f((acc[i].y - mu) * r),
                           gelu_f((acc[i].z - mu) * r), gelu_f((acc[i].w - mu) * r));
    }
}

// ------------- decoder conv_transpose 64->64 as parity-split implicit GEMM -------------
// Double-buffered software pipeline: next tap's X/W tiles are LDG'd into registers
// before the current tap's 2048-FFMA compute block, stored to the alternate smem
// buffer after it -> L2 latency fully hidden behind compute.
// Dynamic smem 96KB: X0[8192] X1[8192] W0[4096] W1[4096] floats. 2 CTAs/SM.
__global__ __launch_bounds__(256, 2) void deconv_gemm(
        const float* __restrict__ X, float* __restrict__ Y,
        const float* __restrict__ W, const float* __restrict__ bias,
        int h_in, int w_in, int hw_sh, int w_sh, int dim, int parity, int ntap) {
    extern __shared__ float dsm[];
    int tid = threadIdx.x;

    // tap tables: (dy, dx) source offset from class coords, wt = ky*3+kx weight tap
    int dy[6], dx[6], wt[6];
    if (dim == 0) {
        if (parity == 0) {
#pragma unroll
            for (int kx = 0; kx < 3; kx++) { dy[kx] = -1; dx[kx] = kx - 1; wt[kx] = kx;
                                             dy[3+kx] = 0; dx[3+kx] = kx - 1; wt[3+kx] = 6 + kx; }
        } else {
#pragma unroll
            for (int kx = 0; kx < 3; kx++) { dy[kx] = 0; dx[kx] = kx - 1; wt[kx] = 3 + kx; }
        }
    } else {
        if (parity == 0) {
#pragma unroll
            for (int ky = 0; ky < 3; ky++) { dy[ky] = ky - 1; dx[ky] = -1; wt[ky] = 3 * ky;
                                             dy[3+ky] = ky - 1; dx[3+ky] = 0; wt[3+ky] = 3 * ky + 2; }
        } else {
#pragma unroll
            for (int ky = 0; ky < 3; ky++) { dy[ky] = ky - 1; dx[ky] = 0; wt[ky] = 3 * ky + 1; }
        }
    }

    int q0 = blockIdx.x * 128;
    int mg = tid >> 1, half = tid & 1;
    int qg = q0 + mg;
    int bg = qg >> hw_sh; int remg = qg & ((1 << hw_sh) - 1);
    int yg = remg >> w_sh; int xg = remg & (w_in - 1);

    float4 acc[8];
#pragma unroll
    for (int i = 0; i < 8; i++) acc[i] = make_float4(0.f, 0.f, 0.f, 0.f);
    int nc = tid & 15, pr = tid >> 4;
    const float4* W4 = (const float4*)W;

    float4 xr[8], wreg[4];
    // prefetch + store tap 0 into buffer 0
    {
        int sy = yg + dy[0], sx = xg + dx[0];
        bool valid = (sy >= 0) && (sy < h_in) && (sx >= 0) && (sx < w_in);
        const float4* src = (const float4*)(X +
            ((((long)bg << hw_sh) + ((long)sy << w_sh) + sx) << 6)) + half * 8;
#pragma unroll
        for (int j = 0; j < 8; j++) xr[j] = valid ? src[j] : make_float4(0.f, 0.f, 0.f, 0.f);
        const float4* wsrc = W4 + wt[0] * 1024;
#pragma unroll
        for (int j = 0; j < 4; j++) wreg[j] = wsrc[tid + j * 256];
        float* Xn = dsm;
#pragma unroll
        for (int j = 0; j < 8; j++) {
            int k = half * 32 + j * 4;
            Xn[(k + 0) * 128 + mg] = xr[j].x; Xn[(k + 1) * 128 + mg] = xr[j].y;
            Xn[(k + 2) * 128 + mg] = xr[j].z; Xn[(k + 3) * 128 + mg] = xr[j].w;
        }
        float4* Wn = (float4*)(dsm + 16384);
#pragma unroll
        for (int j = 0; j < 4; j++) Wn[tid + j * 256] = wreg[j];
    }
    __syncthreads();

#pragma unroll 1
    for (int t = 0; t < ntap; t++) {
        int cur = t & 1, nxt = cur ^ 1;
        bool more = (t + 1 < ntap);
        if (more) {
            int sy = yg + dy[t + 1], sx = xg + dx[t + 1];
            bool valid = (sy >= 0) && (sy < h_in) && (sx >= 0) && (sx < w_in);
            const float4* src = (const float4*)(X +
                ((((long)bg << hw_sh) + ((long)sy << w_sh) + sx) << 6)) + half * 8;
#pragma unroll
            for (int j = 0; j < 8; j++) xr[j] = valid ? src[j] : make_float4(0.f, 0.f, 0.f, 0.f);
            const float4* wsrc = W4 + wt[t + 1] * 1024;
#pragma unroll
            for (int j = 0; j < 4; j++) wreg[j] = wsrc[tid + j * 256];
        }
        // compute over current buffers: 64 k-steps, 32 FFMA per step
        const float*  Xc = dsm + cur * 8192;
        const float4* Wc = (const float4*)(dsm + 16384) + cur * 1024;
#pragma unroll 8
        for (int k = 0; k < 64; k++) {
            float4 wv = Wc[k * 16 + nc];
            const float* xp = Xc + k * 128 + pr * 8;
            float4 xa = *(const float4*)xp;
            float4 xb = *(const float4*)(xp + 4);
            float xs[8] = {xa.x, xa.y, xa.z, xa.w, xb.x, xb.y, xb.z, xb.w};
#pragma unroll
            for (int i = 0; i < 8; i++) {
                acc[i].x = fmaf(xs[i], wv.x, acc[i].x);
                acc[i].y = fmaf(xs[i], wv.y, acc[i].y);
                acc[i].z = fmaf(xs[i], wv.z, acc[i].z);
                acc[i].w = fmaf(xs[i], wv.w, acc[i].w);
            }
        }
        if (more) {
            float* Xn = dsm + nxt * 8192;
#pragma unroll
            for (int j = 0; j < 8; j++) {
                int k = half * 32 + j * 4;
                Xn[(k + 0) * 128 + mg] = xr[j].x; Xn[(k + 1) * 128 + mg] = xr[j].y;
                Xn[(k + 2) * 128 + mg] = xr[j].z; Xn[(k + 3) * 128 + mg] = xr[j].w;
            }
            float4* Wn = (float4*)(dsm + 16384) + nxt * 1024;
#pragma unroll
            for (int j = 0; j < 4; j++) Wn[tid + j * 256] = wreg[j];
        }
        __syncthreads();
    }

    // epilogue: bias + gelu, scatter to interleaved output positions
    float4 bb = __ldg(((const float4*)bias) + nc);
    int h_out = (dim == 0) ? (h_in << 1) : h_in;
    int w_out = (dim == 0) ? w_in : (w_in << 1);
#pragma unroll
    for (int i = 0; i < 8; i++) {
        int q = q0 + pr * 8 + i;
        int b = q >> hw_sh; int rem = q & ((1 << hw_sh) - 1);
        int y = rem >> w_sh; int x = rem & (w_in - 1);
        int oy = (dim == 0) ? (2 * y + parity) : y;
        int ox = (dim == 0) ? x : (2 * x + parity);
        float4 r;
        r.x = gelu_f(acc[i].x + bb.x);
        r.y = gelu_f(acc[i].y + bb.y);
        r.z = gelu_f(acc[i].z + bb.z);
        r.w = gelu_f(acc[i].w + bb.w);
        *((float4*)(Y + ((((long)b * h_out + oy) * w_out + ox) << 6) + nc * 4)) = r;
    }
}

// ------- mask conv(64->4) + softmax + entropy + img pool + masks update + loss -------
// Entropy via single log: H = log S - (sum e_i * t_i)/S, t_i = logit_i - max.
// Fast MUFU paths (__expf/__logf/__fdividef): prob error ~1e-6 << 1e-3 gate.
__global__ void mask_loss(const float* __restrict__ D, const float* __restrict__ mw,
                          const float* __restrict__ mb, const float* __restrict__ img,
                          const float* __restrict__ masks_in, float* __restrict__ masks_out,
                          int h, int w, int dim, int ph, int pw, float invpool,
                          float scale, float* __restrict__ loss) {
    __shared__ float4 ws[576];
    __shared__ float wsum[8];
    int tid = threadIdx.x;
    const float4* mw4 = (const float4*)mw;
    for (int t = tid; t < 576; t += 256) ws[t] = mw4[t];
    __syncthreads();
    int p = blockIdx.x * 256 + tid;
    int hw = h * w;
    int b = p / hw; int rem = p % hw; int oy = rem / w; int ox = rem % w;
    float4 lg = make_float4(__ldg(mb + 0), __ldg(mb + 1), __ldg(mb + 2), __ldg(mb + 3));
    for (int ky = 0; ky < 3; ky++) {
        int iy = oy + ky - 1; if ((unsigned)iy >= (unsigned)h) continue;
        for (int kx = 0; kx < 3; kx++) {
            int ix = ox + kx - 1; if ((unsigned)ix >= (unsigned)w) continue;
            const float4* xp = (const float4*)(D + ((((long)b * h + iy) * w + ix) << 6));
            const float4* wt = &ws[(ky * 3 + kx) * 64];
#pragma unroll
            for (int q = 0; q < 16; q++) {
                float4 xv = xp[q];
                const float4* wr = wt + q * 4;
                lg.x = fmaf(xv.x, wr[0].x, lg.x); lg.y = fmaf(xv.x, wr[0].y, lg.y);
                lg.z = fmaf(xv.x, wr[0].z, lg.z); lg.w = fmaf(xv.x, wr[0].w, lg.w);
                lg.x = fmaf(xv.y, wr[1].x, lg.x); lg.y = fmaf(xv.y, wr[1].y, lg.y);
                lg.z = fmaf(xv.y, wr[1].z, lg.z); lg.w = fmaf(xv.y, wr[1].w, lg.w);
                lg.x = fmaf(xv.z, wr[2].x, lg.x); lg.y = fmaf(xv.z, wr[2].y, lg.y);
                lg.z = fmaf(xv.z, wr[2].z, lg.z); lg.w = fmaf(xv.z, wr[2].w, lg.w);
                lg.x = fmaf(xv.w, wr[3].x, lg.x); lg.y = fmaf(xv.w, wr[3].y, lg.y);
                lg.z = fmaf(xv.w, wr[3].z, lg.z); lg.w = fmaf(xv.w, wr[3].w, lg.w);
            }
        }
    }
    // softmax over 4 + entropy (single log)
    float m = fmaxf(fmaxf(lg.x, lg.y), fmaxf(lg.z, lg.w));
    float t0 = lg.x - m, t1 = lg.y - m, t2 = lg.z - m, t3 = lg.w - m;
    float e0 = __expf(t0), e1 = __expf(t1), e2 = __expf(t2), e3 = __expf(t3);
    float S = e0 + e1 + e2 + e3;
    float inv = __fdividef(1.0f, S);
    float sel = (e1 + 2.0f * e2 + 3.0f * e3) * inv;
    float ent = __logf(S) - (e0 * t0 + e1 * t1 + e2 * t2 + e3 * t3) * inv;
    // average-pooled image at (oy, ox)
    const float* ip = img + (((long)b * 256 + (long)oy * ph) * 256 + (long)ox * pw);
    float s = 0.f;
    for (int a = 0; a < ph; a++)
        for (int cc = 0; cc < pw; cc++) s += ip[a * 256 + cc];
    float ids = s * invpool;
    float d = sel * (1.0f / 3.0f) - ids;
    // masks update (repeat along dim, then += 0.25*sel)
    long src;
    if (dim == 0) src = ((long)b * (h >> 1) + (oy >> 1)) * w + ox;
    else          src = ((long)b * h + oy) * (w >> 1) + (ox >> 1);
    masks_out[p] = masks_in[src] + 0.25f * sel;
    // loss reduction: warp shuffle -> per-warp partials -> single atomicAdd
    float v = ent + d * d;
#pragma unroll
    for (int off = 16; off > 0; off >>= 1) v += __shfl_xor_sync(0xffffffffu, v, off);
    if ((tid & 31) == 0) wsum[tid >> 5] = v;
    __syncthreads();
    if (tid == 0) {
        float s2 = 0.f;
#pragma unroll
        for (int i = 0; i < 8; i++) s2 += wsum[i];
        atomicAdd(loss, s2 * scale);
    }
}

__global__ void zero_loss_k() { g_loss = 0.0f; }
__global__ void finalize_k(float* out) { out[0] = g_loss; }

static inline int ilog2i(int v) { int s = 0; while ((1 << s) < v) s++; return s; }

// ---------------------------------------------------------------------------
extern "C" void kernel_launch(void* const* d_in, const int* in_sizes, int n_in,
                              void* d_out, int out_size) {
    const float* image  = (const float*)d_in[0];
    // d_in[1] = dynamic_cfg (unused)
    const float* w1 = (const float*)d_in[2];  const float* b1 = (const float*)d_in[3];
    const float* w2 = (const float*)d_in[4];  const float* b2 = (const float*)d_in[5];
    const float* w3 = (const float*)d_in[6];  const float* b3 = (const float*)d_in[7];
    const float* w4 = (const float*)d_in[8];  const float* b4 = (const float*)d_in[9];
    const float* up_w = (const float*)d_in[10]; const float* up_b = (const float*)d_in[11];
    const float* mask_w = (const float*)d_in[12]; const float* mask_b = (const float*)d_in[13];
    const float* masks0 = (const float*)d_in[14];
    float* out = (float*)d_out;

    float *e1, *e2, *e3, *dc0, *dc1, *m0, *m1, *lossp;
    cudaGetSymbolAddress((void**)&e1,  g_enc1);
    cudaGetSymbolAddress((void**)&e2,  g_enc2);
    cudaGetSymbolAddress((void**)&e3,  g_enc3);
    cudaGetSymbolAddress((void**)&dc0, g_dec0);
    cudaGetSymbolAddress((void**)&dc1, g_dec1);
    cudaGetSymbolAddress((void**)&m0,  g_m0);
    cudaGetSymbolAddress((void**)&m1,  g_m1);
    cudaGetSymbolAddress((void**)&lossp, g_loss);

    cudaFuncSetAttribute(deconv_gemm, cudaFuncAttributeMaxDynamicSharedMemorySize, 98304);

    zero_loss_k<<<1, 1>>>();

    conv1_trio<<<(8 * 256 * 256) / 256, 256>>>(image, w1, b1, e1);
    conv_s2_trio<16, 16, 256, 16><<<(8 * 128 * 128) / 256, 256>>>(e1, w2, b2, e2);
    conv_s2_trio<16, 32, 128, 16><<<(8 * 64 * 64) / 256, 256>>>(e2, w3, b3, e3);
    conv_s2_trio<32, 64, 64, 16><<<(8 * 32 * 32) / 256, 256>>>(e3, w4, b4, dc0);

    const float lws[6] = {0.1f, 0.1f, 0.5f, 0.5f, 1.0f, 1.0f};
    const float* din = dc0;  float* dout_ = dc1;
    const float* min_ = masks0;
    float* mbuf[2] = {m0, m1};
    int h = 32, w = 32;
    for (int i = 0; i < 6; i++) {
        int dim = i % 2;
        int ho = (dim == 0) ? 2 * h : h;
        int wo = (dim == 0) ? w : 2 * w;
        int px = 8 * ho * wo;
        int cls_px = 8 * h * w;                 // pixels per parity class
        int blocks = cls_px / 128;
        int hw_sh = ilog2i(h * w), w_sh = ilog2i(w);
        deconv_gemm<<<blocks, 256, 98304>>>(din, dout_, up_w, up_b, h, w, hw_sh, w_sh, dim, 0, 6);
        deconv_gemm<<<blocks, 256, 98304>>>(din, dout_, up_w, up_b, h, w, hw_sh, w_sh, dim, 1, 3);
        float* mout = (i == 5) ? (out + 1) : mbuf[i % 2];
        float scale = lws[i] / (float)px;
        int ph = 256 / ho, pw = 256 / wo;
        float invpool = 1.0f / (float)(ph * pw);
        mask_loss<<<px / 256, 256>>>(dout_, mask_w, mask_b, image, min_, mout,
                                     ho, wo, dim, ph, pw, invpool, scale, lossp);
        min_ = mout;
        const float* t = din; din = dout_; dout_ = (float*)t;
        h = ho; w = wo;
    }
    finalize_k<<<1, 1>>>(out);
}